// round 3
// baseline (speedup 1.0000x reference)
#include <cuda_runtime.h>
#include <cstdint>
#include <math.h>

#define H     256
#define TPB   384
#define NR    96            // gate rows per CTA
#define CLSZ  8             // cluster size
#define MAXN  64
#define ENDN  11

// flattened f32 output layout (concat of reference tuple, row-major)
#define NPOFF 0
#define NIOFF 192
#define NVOFF 384
#define EPOFF 448
#define EIOFF 8640
#define EVOFF 16832

struct Params {
    const float *z, *lp_w, *lp_b;
    const float *nWih, *nWhh, *nbih, *nbhh;
    const float *eWih, *eWhh, *ebih, *ebhh;
    const float *nc0w, *nc0b, *nc1w, *nc1b, *nc2w, *nc2b;
    const float *ec0w, *ec0b, *ec1w, *ec1b;
    float *out;
};

struct __align__(16) Smem {
    float4 eWp[64 * NR];     // eWhh slice packed [k4][row]
    float4 nWp[64 * NR];     // nWhh slice packed [k4][row]
    float  P[MAXN * NR];     // cached edge input projections (init = ebih rows)
    float  hbuf[2][H];       // double-buffered broadcast hidden vector
    float  h1v[H];           // this step's node embedding h1
    float  hcarry[H];        // node GRU carry h
    float  xnode[H];         // buf[i-1] (input to node GRU)
    float  part[TPB];        // GEMV partials
    float  gh[NR];
    float  gi[NR];
    float  ebhh_s[NR], nbhh_s[NR], nbih_s[NR], ebih_s[NR];
    float  logits[24];
    float  ecb[12], ncb[24];
    int    ei_ts[MAXN][2];
    float  ep_ts[MAXN][2];
    float  nprob[3];
    int    nidx[3];
    int    all_zero, done, node_ok, activ, xzero;
};

__device__ __forceinline__ uint32_t s2u(const void* p) {
    uint32_t r;
    asm("{ .reg .u64 t; cvta.to.shared.u64 t, %1; cvt.u32.u64 %0, t; }" : "=r"(r) : "l"(p));
    return r;
}
__device__ __forceinline__ void st_cluster_f32(uint32_t local_addr, uint32_t rk, float v) {
    uint32_t pa;
    asm volatile("mapa.shared::cluster.u32 %0, %1, %2;" : "=r"(pa) : "r"(local_addr), "r"(rk));
    asm volatile("st.shared::cluster.f32 [%0], %1;" :: "r"(pa), "f"(v) : "memory");
}
__device__ __forceinline__ void cluster_sync_() {
    asm volatile("barrier.cluster.arrive.aligned;" ::: "memory");
    asm volatile("barrier.cluster.wait.aligned;" ::: "memory");
}
__device__ __forceinline__ float wred(float v) {
    v += __shfl_xor_sync(0xffffffffu, v, 16);
    v += __shfl_xor_sync(0xffffffffu, v, 8);
    v += __shfl_xor_sync(0xffffffffu, v, 4);
    v += __shfl_xor_sync(0xffffffffu, v, 2);
    v += __shfl_xor_sync(0xffffffffu, v, 1);
    return v;
}
__device__ __forceinline__ float sigf(float x) { return 1.f / (1.f + expf(-x)); }

__global__ void Generator_34746285425383_kernel(Params p) {
    extern __shared__ __align__(16) unsigned char smem_raw[];
    Smem* s = reinterpret_cast<Smem*>(smem_raw);

    const int tid  = threadIdx.x;
    const int lane = tid & 31;
    const int w    = tid >> 5;
    const int q    = tid / NR;      // column quarter (0..3)
    const int r    = tid % NR;      // local gate row
    uint32_t rank;
    asm("mov.u32 %0, %%cluster_ctarank;" : "=r"(rank));
    const int gbase = (int)rank * 32;

    auto grow = [&](int l) { return ((l >> 5) << 8) + gbase + (l & 31); };

    // ================= init =================
    for (int idx = tid; idx < 64 * NR; idx += TPB) {
        int k4 = idx / NR, l = idx % NR;
        int row = grow(l);
        s->eWp[idx] = reinterpret_cast<const float4*>(p.eWhh + row * H)[k4];
        s->nWp[idx] = reinterpret_cast<const float4*>(p.nWhh + row * H)[k4];
        s->P[idx]   = p.ebih[grow(idx % NR)];   // proj of zero embedding = bias
    }
    if (tid < NR) {
        int row = grow(tid);
        s->ebhh_s[tid] = p.ebhh[row];
        s->nbhh_s[tid] = p.nbhh[row];
        s->nbih_s[tid] = p.nbih[row];
        s->ebih_s[tid] = p.ebih[row];
    }
    if (tid < 9)  s->ecb[tid] = (tid < 5) ? p.ec0b[tid] : p.ec1b[tid - 5];
    if (tid < 21) s->ncb[tid] = (tid < 12) ? p.nc0b[tid]
                               : (tid < 17) ? p.nc1b[tid - 12] : p.nc2b[tid - 17];
    if (tid < H) {
        float acc = p.lp_b[tid];
        const float* wr = p.lp_w + tid * 128;
        #pragma unroll 8
        for (int k = 0; k < 128; k++) acc = fmaf(wr[k], p.z[k], acc);
        s->hcarry[tid] = acc;
        s->xnode[tid]  = 0.f;
    }
    if (tid == 0) { s->done = 0; s->xzero = 1; }

    // classifier weight rows in registers
    float ew[8], na[8], nb[8];
    #pragma unroll
    for (int k = 0; k < 8; k++) { ew[k] = 0.f; na[k] = 0.f; nb[k] = 0.f; }
    if (w < 9) {
        const float* base = (w < 5) ? p.ec0w + w * H : p.ec1w + (w - 5) * H;
        #pragma unroll
        for (int k = 0; k < 8; k++) ew[k] = base[lane + 32 * k];
    }
    if (w < 12) {
        const float* base = p.nc0w + w * H;
        #pragma unroll
        for (int k = 0; k < 8; k++) na[k] = base[lane + 32 * k];
    }
    if (w < 9) {
        const float* base = (w < 5) ? p.nc1w + w * H : p.nc2w + (w - 5) * H;
        #pragma unroll
        for (int k = 0; k < 8; k++) nb[k] = base[lane + 32 * k];
    }
    __syncthreads();
    cluster_sync_();

    auto edge_logits = [&](const float* v) {
        if (w < 9) {
            float sum = 0.f;
            #pragma unroll
            for (int k = 0; k < 8; k++) sum = fmaf(ew[k], v[lane + 32 * k], sum);
            sum = wred(sum);
            if (lane == 0) s->logits[w] = sum + s->ecb[w];
        }
    };

    int cur = 0;
    for (int i = 0; i < MAXN; i++) {
        const int xz = s->xzero;

        // ---------- node tick: gh = hcarry @ nWhh_slice ----------
        {
            float acc = 0.f;
            const float4* xv = reinterpret_cast<const float4*>(s->hcarry) + q * 16;
            #pragma unroll
            for (int j = 0; j < 16; j++) {
                float4 wv = s->nWp[(q * 16 + j) * NR + r];
                float4 xx = xv[j];
                acc = fmaf(wv.x, xx.x, fmaf(wv.y, xx.y, fmaf(wv.z, xx.z, fmaf(wv.w, xx.w, acc))));
            }
            s->part[tid] = acc;
        }
        __syncthreads();
        if (tid < NR)
            s->gh[tid] = s->part[tid] + s->part[NR + tid] + s->part[2 * NR + tid]
                       + s->part[3 * NR + tid] + s->nbhh_s[tid];
        __syncthreads();
        // gi = xnode @ nWih (from L2), skipped if xnode == 0
        if (!xz) {
            float acc = 0.f;
            int row = grow(r);
            const float4* wr = reinterpret_cast<const float4*>(p.nWih + row * H) + q * 16;
            const float4* xv = reinterpret_cast<const float4*>(s->xnode) + q * 16;
            #pragma unroll
            for (int j = 0; j < 16; j++) {
                float4 wv = wr[j];
                float4 xx = xv[j];
                acc = fmaf(wv.x, xx.x, fmaf(wv.y, xx.y, fmaf(wv.z, xx.z, fmaf(wv.w, xx.w, acc))));
            }
            s->part[tid] = acc;
        }
        __syncthreads();
        if (tid < NR)
            s->gi[tid] = s->nbih_s[tid] + (xz ? 0.f
                        : (s->part[tid] + s->part[NR + tid] + s->part[2 * NR + tid] + s->part[3 * NR + tid]));
        __syncthreads();
        if (tid < 32) {
            float hr = s->gh[tid], hz = s->gh[tid + 32], hn = s->gh[tid + 64];
            float ir = s->gi[tid], iz = s->gi[tid + 32], inn = s->gi[tid + 64];
            float rg = sigf(ir + hr);
            float zg = sigf(iz + hz);
            float nn = tanhf(inn + rg * hn);
            float hold = s->hcarry[gbase + tid];
            float hv = (1.f - zg) * nn + zg * hold;
            uint32_t a = s2u(&s->hbuf[cur ^ 1][gbase + tid]);
            #pragma unroll
            for (int rk = 0; rk < CLSZ; rk++) st_cluster_f32(a, rk, hv);
        }
        cluster_sync_();
        cur ^= 1;

        // h1 snapshot + node classification
        for (int k = tid; k < H; k += TPB) s->h1v[k] = s->hbuf[cur][k];
        {
            const float* v = s->hbuf[cur];
            if (w < 12) {
                float sum = 0.f;
                #pragma unroll
                for (int k = 0; k < 8; k++) sum = fmaf(na[k], v[lane + 32 * k], sum);
                sum = wred(sum);
                if (lane == 0) s->logits[w] = sum + s->ncb[w];
            }
            if (w < 9) {
                float sum = 0.f;
                #pragma unroll
                for (int k = 0; k < 8; k++) sum = fmaf(nb[k], v[lane + 32 * k], sum);
                sum = wred(sum);
                if (lane == 0) s->logits[12 + w] = sum + s->ncb[12 + w];
            }
        }
        __syncthreads();
        if (tid == 0) {
            // classifier 0 (12), 1 (5), 2 (4)
            int starts[4] = {0, 12, 17, 21};
            #pragma unroll
            for (int c = 0; c < 3; c++) {
                float m = -1e30f; int b = 0;
                for (int j2 = starts[c]; j2 < starts[c + 1]; j2++) {
                    float l2 = s->logits[j2];
                    if (l2 > m) { m = l2; b = j2 - starts[c]; }
                }
                float se = 0.f;
                for (int j2 = starts[c]; j2 < starts[c + 1]; j2++) se += expf(s->logits[j2] - m);
                s->nprob[c] = 1.f / se;
                s->nidx[c] = b;
            }
            s->all_zero = 1;
        }
        __syncthreads();

        if (i == 0) {   // edge classification of h1 (inner t=0, no update)
            edge_logits(s->hbuf[cur]);
            __syncthreads();
            if (tid == 0) {
                float m0 = -1e30f; int b0 = 0;
                for (int j2 = 0; j2 < 5; j2++) { float l2 = s->logits[j2]; if (l2 > m0) { m0 = l2; b0 = j2; } }
                float se0 = 0.f; for (int j2 = 0; j2 < 5; j2++) se0 += expf(s->logits[j2] - m0);
                float m1 = -1e30f; int b1 = 0;
                for (int j2 = 5; j2 < 9; j2++) { float l2 = s->logits[j2]; if (l2 > m1) { m1 = l2; b1 = j2 - 5; } }
                float se1 = 0.f; for (int j2 = 5; j2 < 9; j2++) se1 += expf(s->logits[j2] - m1);
                s->ei_ts[0][0] = b0; s->ei_ts[0][1] = b1;
                s->ep_ts[0][0] = 1.f / se0; s->ep_ts[0][1] = 1.f / se1;
            }
            __syncthreads();
        }

        // ---------- edge scan: t = 0..i-1 ----------
        for (int t = 0; t < i; t++) {
            const int src = i - 1 - t;
            {
                float acc = 0.f;
                const float4* xv = reinterpret_cast<const float4*>(s->hbuf[cur]) + q * 16;
                #pragma unroll
                for (int j = 0; j < 16; j++) {
                    float4 wv = s->eWp[(q * 16 + j) * NR + r];
                    float4 xx = xv[j];
                    acc = fmaf(wv.x, xx.x, fmaf(wv.y, xx.y, fmaf(wv.z, xx.z, fmaf(wv.w, xx.w, acc))));
                }
                s->part[tid] = acc;
            }
            __syncthreads();
            if (tid < 32) {
                float hr = s->part[tid]      + s->part[NR + tid]      + s->part[2 * NR + tid]      + s->part[3 * NR + tid]      + s->ebhh_s[tid];
                float hz = s->part[tid + 32] + s->part[NR + tid + 32] + s->part[2 * NR + tid + 32] + s->part[3 * NR + tid + 32] + s->ebhh_s[tid + 32];
                float hn = s->part[tid + 64] + s->part[NR + tid + 64] + s->part[2 * NR + tid + 64] + s->part[3 * NR + tid + 64] + s->ebhh_s[tid + 64];
                const float* Pr = s->P + src * NR;
                float ir = Pr[tid], iz = Pr[tid + 32], inn = Pr[tid + 64];
                float rg = sigf(ir + hr);
                float zg = sigf(iz + hz);
                float nn = tanhf(inn + rg * hn);
                float hold = s->hbuf[cur][gbase + tid];
                float hv = (1.f - zg) * nn + zg * hold;
                uint32_t a = s2u(&s->hbuf[cur ^ 1][gbase + tid]);
                #pragma unroll
                for (int rk = 0; rk < CLSZ; rk++) st_cluster_f32(a, rk, hv);
            }
            cluster_sync_();
            cur ^= 1;

            edge_logits(s->hbuf[cur]);
            __syncthreads();
            if (tid == 0) {
                float m0 = -1e30f; int b0 = 0;
                for (int j2 = 0; j2 < 5; j2++) { float l2 = s->logits[j2]; if (l2 > m0) { m0 = l2; b0 = j2; } }
                float se0 = 0.f; for (int j2 = 0; j2 < 5; j2++) se0 += expf(s->logits[j2] - m0);
                float m1 = -1e30f; int b1 = 0;
                for (int j2 = 5; j2 < 9; j2++) { float l2 = s->logits[j2]; if (l2 > m1) { m1 = l2; b1 = j2 - 5; } }
                float se1 = 0.f; for (int j2 = 5; j2 < 9; j2++) se1 += expf(s->logits[j2] - m1);
                s->ei_ts[t][0] = b0; s->ei_ts[t][1] = b1;
                s->ep_ts[t][0] = 1.f / se0; s->ep_ts[t][1] = 1.f / se1;
                if (b0 != 0) s->all_zero = 0;
            }
            __syncthreads();
        }

        // ---------- decisions ----------
        if (tid == 0) {
            int is_end   = (s->nidx[0] == ENDN);
            int no_edges = (i > 0) && s->all_zero;
            int active   = !s->done;
            int nok      = active && !is_end && !no_edges;
            s->node_ok = nok;
            s->activ   = active;
            s->done    = s->done | is_end | no_edges;
            s->xzero   = !nok;
        }
        __syncthreads();
        const int nok = s->node_ok;
        const int active = s->activ;

        if (active) {
            const float* sv = (nok && i > 0) ? s->hbuf[cur] : s->h1v;
            for (int k = tid; k < H; k += TPB) s->hcarry[k] = sv[k];
        }
        for (int k = tid; k < H; k += TPB) s->xnode[k] = nok ? s->h1v[k] : 0.f;
        __syncthreads();

        // freeze: P[i] = h1 @ eWih_rows + ebih
        if (nok) {
            float acc = 0.f;
            int row = grow(r);
            const float4* wr = reinterpret_cast<const float4*>(p.eWih + row * H) + q * 16;
            const float4* xv = reinterpret_cast<const float4*>(s->h1v) + q * 16;
            #pragma unroll
            for (int j = 0; j < 16; j++) {
                float4 wv = wr[j];
                float4 xx = xv[j];
                acc = fmaf(wv.x, xx.x, fmaf(wv.y, xx.y, fmaf(wv.z, xx.z, fmaf(wv.w, xx.w, acc))));
            }
            s->part[tid] = acc;
            __syncthreads();
            if (tid < NR)
                s->P[i * NR + tid] = s->part[tid] + s->part[NR + tid] + s->part[2 * NR + tid]
                                   + s->part[3 * NR + tid] + s->ebih_s[tid];
        }
        __syncthreads();

        // ---------- outputs (rank 0) ----------
        if (rank == 0) {
            if (tid == 0) {
                #pragma unroll
                for (int c = 0; c < 3; c++) {
                    p.out[NPOFF + i * 3 + c] = nok ? s->nprob[c] : 0.f;
                    p.out[NIOFF + i * 3 + c] = (float)s->nidx[c];
                }
                p.out[NVOFF + i] = nok ? 1.f : 0.f;
            }
            if (tid < 64) {
                int j  = tid;
                int t2 = (j < i) ? (i - 1 - j) : 0;
                int ev = (j < i) && nok && (i > 0);
                p.out[EPOFF + (i * 64 + j) * 2 + 0] = ev ? s->ep_ts[t2][0] : 0.f;
                p.out[EPOFF + (i * 64 + j) * 2 + 1] = ev ? s->ep_ts[t2][1] : 0.f;
                p.out[EIOFF + (i * 64 + j) * 2 + 0] = (float)s->ei_ts[t2][0];
                p.out[EIOFF + (i * 64 + j) * 2 + 1] = (float)s->ei_ts[t2][1];
                p.out[EVOFF + i * 64 + j] = ev ? 1.f : 0.f;
            }
        }
        __syncthreads();
    }
    cluster_sync_();
}

extern "C" void kernel_launch(void* const* d_in, const int* in_sizes, int n_in,
                              void* d_out, int out_size) {
    Params p;
    p.z    = (const float*)d_in[0];
    p.lp_w = (const float*)d_in[1];
    p.lp_b = (const float*)d_in[2];
    p.nWih = (const float*)d_in[3];
    p.nWhh = (const float*)d_in[4];
    p.nbih = (const float*)d_in[5];
    p.nbhh = (const float*)d_in[6];
    p.eWih = (const float*)d_in[7];
    p.eWhh = (const float*)d_in[8];
    p.ebih = (const float*)d_in[9];
    p.ebhh = (const float*)d_in[10];
    p.nc0w = (const float*)d_in[11];
    p.nc0b = (const float*)d_in[12];
    p.nc1w = (const float*)d_in[13];
    p.nc1b = (const float*)d_in[14];
    p.nc2w = (const float*)d_in[15];
    p.nc2b = (const float*)d_in[16];
    p.ec0w = (const float*)d_in[17];
    p.ec0b = (const float*)d_in[18];
    p.ec1w = (const float*)d_in[19];
    p.ec1b = (const float*)d_in[20];
    p.out  = (float*)d_out;

    cudaFuncSetAttribute(Generator_34746285425383_kernel,
                         cudaFuncAttributeMaxDynamicSharedMemorySize,
                         (int)sizeof(Smem));

    cudaLaunchConfig_t cfg = {};
    cfg.gridDim  = dim3(CLSZ, 1, 1);
    cfg.blockDim = dim3(TPB, 1, 1);
    cfg.dynamicSmemBytes = sizeof(Smem);
    cfg.stream = 0;
    cudaLaunchAttribute attrs[1];
    attrs[0].id = cudaLaunchAttributeClusterDimension;
    attrs[0].val.clusterDim.x = CLSZ;
    attrs[0].val.clusterDim.y = 1;
    attrs[0].val.clusterDim.z = 1;
    cfg.attrs = attrs;
    cfg.numAttrs = 1;
    cudaLaunchKernelEx(&cfg, Generator_34746285425383_kernel, p);
}

// round 4
// speedup vs baseline: 1.1775x; 1.1775x over previous
#include <cuda_runtime.h>
#include <cstdint>
#include <math.h>

#define H     256
#define TPB   384
#define CLSZ  16
#define EPB   16            // h elements per CTA
#define NR    48            // gate rows per CTA (3*EPB)
#define MAXN  64
#define ENDN  11

// flattened f32 output layout (concat of reference tuple, row-major)
#define NPOFF 0
#define NIOFF 192
#define NVOFF 384
#define EPOFF 448
#define EIOFF 8640
#define EVOFF 16832

struct Params {
    const float *z, *lp_w, *lp_b;
    const float *nWih, *nWhh, *nbih, *nbhh;
    const float *eWih, *eWhh, *ebih, *ebhh;
    const float *nc0w, *nc0b, *nc1w, *nc1b, *nc2w, *nc2b;
    const float *ec0w, *ec0b, *ec1w, *ec1b;
    float *out;
};

struct __align__(16) Smem {
    float4 eWp[64 * NR];     // eWhh slice  packed [k4][row]
    float4 nWp[64 * NR];     // nWhh slice
    float4 eIp[64 * NR];     // eWih slice
    float4 nIp[64 * NR];     // nWih slice
    float  P[MAXN * NR];     // cached edge input projections (init = ebih rows)
    float  hbuf[2][H];       // double-buffered broadcast hidden vector
    float  h1v[H];           // this step's node embedding h1
    float  hcarry[H];        // node GRU carry h
    float  xnode[H];         // buf[i-1] (input to node GRU)
    float  part[TPB];        // GEMV partials
    float  parti[TPB];       // second partials (node gi)
    float  gh[NR];
    float  gi[NR];
    float  ebhh_s[NR], nbhh_s[NR], nbih_s[NR], ebih_s[NR];
    float  logits[28];
    float  ecb[9], ncb[21];
    float  ep_ts[MAXN][2];
    int    ei_ts[MAXN][2];
    float  nprob[3];
    int    nidx[3];
    int    all_zero, done, node_ok, activ, xzero;
};

__device__ __forceinline__ uint32_t s2u(const void* p) {
    uint32_t r;
    asm("{ .reg .u64 t; cvta.to.shared.u64 t, %1; cvt.u32.u64 %0, t; }" : "=r"(r) : "l"(p));
    return r;
}
__device__ __forceinline__ void st_cluster_f32(uint32_t local_addr, uint32_t rk, float v) {
    uint32_t pa;
    asm volatile("mapa.shared::cluster.u32 %0, %1, %2;" : "=r"(pa) : "r"(local_addr), "r"(rk));
    asm volatile("st.shared::cluster.f32 [%0], %1;" :: "r"(pa), "f"(v) : "memory");
}
__device__ __forceinline__ void cluster_sync_() {
    asm volatile("barrier.cluster.arrive.aligned;" ::: "memory");
    asm volatile("barrier.cluster.wait.aligned;" ::: "memory");
}
__device__ __forceinline__ float wred(float v) {
    v += __shfl_xor_sync(0xffffffffu, v, 16);
    v += __shfl_xor_sync(0xffffffffu, v, 8);
    v += __shfl_xor_sync(0xffffffffu, v, 4);
    v += __shfl_xor_sync(0xffffffffu, v, 2);
    v += __shfl_xor_sync(0xffffffffu, v, 1);
    return v;
}
__device__ __forceinline__ float sigf(float x) { return 1.f / (1.f + __expf(-x)); }

__global__ void __launch_bounds__(TPB, 1)
Generator_34746285425383_kernel(Params p) {
    extern __shared__ __align__(16) unsigned char smem_raw[];
    Smem* s = reinterpret_cast<Smem*>(smem_raw);

    const int tid  = threadIdx.x;
    const int lane = tid & 31;
    const int w    = tid >> 5;
    const int q    = tid / NR;      // column-chunk (0..7), 8 float4 each
    const int r    = tid % NR;      // local gate row
    uint32_t rank;
    asm("mov.u32 %0, %%cluster_ctarank;" : "=r"(rank));
    const int gbase = (int)rank * EPB;

    auto grow = [&](int l) { return ((l >> 4) << 8) + gbase + (l & 15); };

    // ================= init =================
    {
        const float* srcs[4] = { p.eWhh, p.nWhh, p.eWih, p.nWih };
        float4* dsts[4] = { s->eWp, s->nWp, s->eIp, s->nIp };
        #pragma unroll
        for (int m = 0; m < 4; m++) {
            for (int l = w; l < NR; l += 12) {
                const float4* src = reinterpret_cast<const float4*>(srcs[m] + grow(l) * H);
                #pragma unroll
                for (int j = 0; j < 2; j++) {
                    int k4 = lane + 32 * j;
                    dsts[m][k4 * NR + l] = src[k4];
                }
            }
        }
    }
    for (int idx = tid; idx < MAXN * NR; idx += TPB)
        s->P[idx] = p.ebih[grow(idx % NR)];       // proj of zero embedding = bias
    if (tid < NR) {
        int row = grow(tid);
        s->ebhh_s[tid] = p.ebhh[row];
        s->nbhh_s[tid] = p.nbhh[row];
        s->nbih_s[tid] = p.nbih[row];
        s->ebih_s[tid] = p.ebih[row];
    }
    if (tid < 9)  s->ecb[tid] = (tid < 5) ? p.ec0b[tid] : p.ec1b[tid - 5];
    if (tid < 21) s->ncb[tid] = (tid < 12) ? p.nc0b[tid]
                               : (tid < 17) ? p.nc1b[tid - 12] : p.nc2b[tid - 17];
    if (tid < H) {
        float acc = p.lp_b[tid];
        const float* wr = p.lp_w + tid * 128;
        #pragma unroll 8
        for (int k = 0; k < 128; k++) acc = fmaf(wr[k], p.z[k], acc);
        s->hcarry[tid] = acc;
        s->xnode[tid]  = 0.f;
    }
    if (tid == 0) { s->done = 0; s->xzero = 1; }

    // classifier weight rows in registers (warps 1..9)
    float ew[8], nw0[8], nw1[8], nw2[8];
    #pragma unroll
    for (int k = 0; k < 8; k++) { ew[k] = 0.f; nw0[k] = 0.f; nw1[k] = 0.f; nw2[k] = 0.f; }
    if (w >= 1 && w <= 9) {
        int wc = w - 1;
        const float* eb = (wc < 5) ? p.ec0w + wc * H : p.ec1w + (wc - 5) * H;
        auto nbase = [&](int n) {
            return (n < 12) ? p.nc0w + n * H : (n < 17) ? p.nc1w + (n - 12) * H : p.nc2w + (n - 17) * H;
        };
        const float* n0 = nbase(wc);
        const float* n1 = nbase(wc + 9);
        const float* n2 = (wc < 3) ? nbase(wc + 18) : n0;
        #pragma unroll
        for (int k = 0; k < 8; k++) {
            ew[k]  = eb[lane + 32 * k];
            nw0[k] = n0[lane + 32 * k];
            nw1[k] = n1[lane + 32 * k];
            nw2[k] = (wc < 3) ? n2[lane + 32 * k] : 0.f;
        }
    }
    __syncthreads();
    cluster_sync_();

    auto cls_edge = [&](const float* v) {
        if (w >= 1 && w <= 9) {
            float sum = 0.f;
            #pragma unroll
            for (int k = 0; k < 8; k++) sum = fmaf(ew[k], v[lane + 32 * k], sum);
            sum = wred(sum);
            if (lane == 0) s->logits[w - 1] = sum + s->ecb[w - 1];
        }
    };
    auto cls_node = [&](const float* v) {
        if (w >= 1 && w <= 9) {
            int wc = w - 1;
            float s0 = 0.f, s1 = 0.f, s2 = 0.f;
            #pragma unroll
            for (int k = 0; k < 8; k++) {
                float x = v[lane + 32 * k];
                s0 = fmaf(nw0[k], x, s0);
                s1 = fmaf(nw1[k], x, s1);
                s2 = fmaf(nw2[k], x, s2);
            }
            s0 = wred(s0); s1 = wred(s1); s2 = wred(s2);
            if (lane == 0) {
                s->logits[wc]     = s0 + s->ncb[wc];
                s->logits[wc + 9] = s1 + s->ncb[wc + 9];
                if (wc < 3) s->logits[wc + 18] = s2 + s->ncb[wc + 18];
            }
        }
    };
    auto soft_edge = [&](int idx, int count_az) {
        // executed by warp 1 lanes 0,1
        int base = lane ? 5 : 0;
        int n    = lane ? 4 : 5;
        float m = -1e30f; int b = 0;
        for (int j = 0; j < n; j++) {
            float L = s->logits[base + j];
            if (L > m) { m = L; b = j; }
        }
        float se = 0.f;
        for (int j = 0; j < n; j++) se += __expf(s->logits[base + j] - m);
        s->ei_ts[idx][lane] = b;
        s->ep_ts[idx][lane] = 1.f / se;
        if (count_az && lane == 0 && b != 0) s->all_zero = 0;
    };
    auto soft_node = [&]() {
        // executed by warp 1 lanes 0,1,2
        const int starts[3] = {0, 12, 17};
        const int cnts[3]   = {12, 5, 4};
        int base = starts[lane], n = cnts[lane];
        float m = -1e30f; int b = 0;
        for (int j = 0; j < n; j++) {
            float L = s->logits[base + j];
            if (L > m) { m = L; b = j; }
        }
        float se = 0.f;
        for (int j = 0; j < n; j++) se += __expf(s->logits[base + j] - m);
        s->nprob[lane] = 1.f / se;
        s->nidx[lane]  = b;
    };

    int cur = 0;
    for (int i = 0; i < MAXN; i++) {
        const int xz = s->xzero;

        // ---------- node tick ----------
        {
            float acc = 0.f, acci = 0.f;
            const float4* hv4 = reinterpret_cast<const float4*>(s->hcarry);
            const float4* xv4 = reinterpret_cast<const float4*>(s->xnode);
            #pragma unroll
            for (int j = 0; j < 8; j++) {
                int k4 = q * 8 + j;
                float4 wv = s->nWp[k4 * NR + r];
                float4 xx = hv4[k4];
                acc = fmaf(wv.x, xx.x, fmaf(wv.y, xx.y, fmaf(wv.z, xx.z, fmaf(wv.w, xx.w, acc))));
                if (!xz) {
                    float4 wi = s->nIp[k4 * NR + r];
                    float4 xi = xv4[k4];
                    acci = fmaf(wi.x, xi.x, fmaf(wi.y, xi.y, fmaf(wi.z, xi.z, fmaf(wi.w, xi.w, acci))));
                }
            }
            s->part[tid]  = acc;
            s->parti[tid] = acci;
        }
        __syncthreads();
        if (tid < NR) {
            float sg = 0.f, si = 0.f;
            #pragma unroll
            for (int qq = 0; qq < 8; qq++) { sg += s->part[qq * NR + tid]; si += s->parti[qq * NR + tid]; }
            s->gh[tid] = sg + s->nbhh_s[tid];
            s->gi[tid] = s->nbih_s[tid] + (xz ? 0.f : si);
        }
        if (tid == 0) s->all_zero = 1;
        __syncthreads();
        if (w == 0) {
            int e = lane & 15;
            float hr = s->gh[e], hz = s->gh[EPB + e], hn = s->gh[2 * EPB + e];
            float ir = s->gi[e], iz = s->gi[EPB + e], inn = s->gi[2 * EPB + e];
            float rg = sigf(ir + hr);
            float zg = sigf(iz + hz);
            float nn = tanhf(inn + rg * hn);
            float hold = s->hcarry[gbase + e];
            float hv = (1.f - zg) * nn + zg * hold;
            uint32_t a = s2u(&s->hbuf[cur ^ 1][gbase + e]);
            int r0 = (lane >> 4) * 8;
            #pragma unroll
            for (int k = 0; k < 8; k++) st_cluster_f32(a, r0 + k, hv);
        }
        cluster_sync_();
        cur ^= 1;
        for (int k = tid; k < H; k += TPB) s->h1v[k] = s->hbuf[cur][k];

        // ---------- edge ticks t = 0..i-1 ----------
        for (int t = 0; t < i; t++) {
            const int src = i - 1 - t;
            {
                float acc = 0.f;
                const float4* xv = reinterpret_cast<const float4*>(s->hbuf[cur]);
                #pragma unroll
                for (int j = 0; j < 8; j++) {
                    int k4 = q * 8 + j;
                    float4 wv = s->eWp[k4 * NR + r];
                    float4 xx = xv[k4];
                    acc = fmaf(wv.x, xx.x, fmaf(wv.y, xx.y, fmaf(wv.z, xx.z, fmaf(wv.w, xx.w, acc))));
                }
                s->part[tid] = acc;
            }
            __syncthreads();
            if (tid < NR) {
                float sg = 0.f;
                #pragma unroll
                for (int qq = 0; qq < 8; qq++) sg += s->part[qq * NR + tid];
                s->gh[tid] = sg + s->ebhh_s[tid];
            }
            __syncthreads();
            if (w == 0) {
                int e = lane & 15;
                float hr = s->gh[e], hz = s->gh[EPB + e], hn = s->gh[2 * EPB + e];
                const float* Pr = s->P + src * NR;
                float ir = Pr[e], iz = Pr[EPB + e], inn = Pr[2 * EPB + e];
                float rg = sigf(ir + hr);
                float zg = sigf(iz + hz);
                float nn = tanhf(inn + rg * hn);
                float hold = s->hbuf[cur][gbase + e];
                float hv = (1.f - zg) * nn + zg * hold;
                uint32_t a = s2u(&s->hbuf[cur ^ 1][gbase + e]);
                int r0 = (lane >> 4) * 8;
                #pragma unroll
                for (int k = 0; k < 8; k++) st_cluster_f32(a, r0 + k, hv);
            } else if (w <= 9) {
                // classify hbuf[cur]: t==0 -> node classifiers of h1; t>=1 -> edge of he_t
                if (t == 0) cls_node(s->hbuf[cur]); else cls_edge(s->hbuf[cur]);
                asm volatile("bar.sync 1, 288;" ::: "memory");
                if (w == 1) {
                    if (t == 0) { if (lane < 3) soft_node(); }
                    else        { if (lane < 2) soft_edge(t - 1, 1); }
                }
            }
            cluster_sync_();
            cur ^= 1;
        }

        // ---------- drain: final classifications ----------
        if (i == 0) {
            cls_node(s->hbuf[cur]);
            __syncthreads();
            if (w == 1 && lane < 3) soft_node();
            __syncthreads();
        }
        cls_edge(s->hbuf[cur]);
        __syncthreads();
        if (w == 1 && lane < 2) soft_edge((i > 0) ? (i - 1) : 0, (i > 0) ? 1 : 0);
        __syncthreads();

        // ---------- decisions ----------
        if (tid == 0) {
            int is_end   = (s->nidx[0] == ENDN);
            int no_edges = (i > 0) && s->all_zero;
            int active   = !s->done;
            int nok      = active && !is_end && !no_edges;
            s->node_ok = nok;
            s->activ   = active;
            s->done    = s->done | is_end | no_edges;
            s->xzero   = !nok;
        }
        __syncthreads();
        const int nok    = s->node_ok;
        const int active = s->activ;

        if (active) {
            const float* sv = (nok && i > 0) ? s->hbuf[cur] : s->h1v;
            for (int k = tid; k < H; k += TPB) s->hcarry[k] = sv[k];
        }
        for (int k = tid; k < H; k += TPB) s->xnode[k] = nok ? s->h1v[k] : 0.f;
        __syncthreads();

        // freeze: P[i] = h1 @ eWih_rows + ebih
        if (nok) {
            float acc = 0.f;
            const float4* xv = reinterpret_cast<const float4*>(s->h1v);
            #pragma unroll
            for (int j = 0; j < 8; j++) {
                int k4 = q * 8 + j;
                float4 wv = s->eIp[k4 * NR + r];
                float4 xx = xv[k4];
                acc = fmaf(wv.x, xx.x, fmaf(wv.y, xx.y, fmaf(wv.z, xx.z, fmaf(wv.w, xx.w, acc))));
            }
            s->part[tid] = acc;
            __syncthreads();
            if (tid < NR) {
                float sg = 0.f;
                #pragma unroll
                for (int qq = 0; qq < 8; qq++) sg += s->part[qq * NR + tid];
                s->P[i * NR + tid] = sg + s->ebih_s[tid];
            }
        }
        __syncthreads();

        // ---------- outputs (rank 0) ----------
        if (rank == 0) {
            if (tid == 0) {
                #pragma unroll
                for (int c = 0; c < 3; c++) {
                    p.out[NPOFF + i * 3 + c] = nok ? s->nprob[c] : 0.f;
                    p.out[NIOFF + i * 3 + c] = (float)s->nidx[c];
                }
                p.out[NVOFF + i] = nok ? 1.f : 0.f;
            }
            if (tid < 64) {
                int j  = tid;
                int t2 = (j < i) ? (i - 1 - j) : 0;
                int ev = (j < i) && nok && (i > 0);
                p.out[EPOFF + (i * 64 + j) * 2 + 0] = ev ? s->ep_ts[t2][0] : 0.f;
                p.out[EPOFF + (i * 64 + j) * 2 + 1] = ev ? s->ep_ts[t2][1] : 0.f;
                p.out[EIOFF + (i * 64 + j) * 2 + 0] = (float)s->ei_ts[t2][0];
                p.out[EIOFF + (i * 64 + j) * 2 + 1] = (float)s->ei_ts[t2][1];
                p.out[EVOFF + i * 64 + j] = ev ? 1.f : 0.f;
            }
        }
        __syncthreads();
    }
    cluster_sync_();
}

extern "C" void kernel_launch(void* const* d_in, const int* in_sizes, int n_in,
                              void* d_out, int out_size) {
    Params p;
    p.z    = (const float*)d_in[0];
    p.lp_w = (const float*)d_in[1];
    p.lp_b = (const float*)d_in[2];
    p.nWih = (const float*)d_in[3];
    p.nWhh = (const float*)d_in[4];
    p.nbih = (const float*)d_in[5];
    p.nbhh = (const float*)d_in[6];
    p.eWih = (const float*)d_in[7];
    p.eWhh = (const float*)d_in[8];
    p.ebih = (const float*)d_in[9];
    p.ebhh = (const float*)d_in[10];
    p.nc0w = (const float*)d_in[11];
    p.nc0b = (const float*)d_in[12];
    p.nc1w = (const float*)d_in[13];
    p.nc1b = (const float*)d_in[14];
    p.nc2w = (const float*)d_in[15];
    p.nc2b = (const float*)d_in[16];
    p.ec0w = (const float*)d_in[17];
    p.ec0b = (const float*)d_in[18];
    p.ec1w = (const float*)d_in[19];
    p.ec1b = (const float*)d_in[20];
    p.out  = (float*)d_out;

    cudaFuncSetAttribute(Generator_34746285425383_kernel,
                         cudaFuncAttributeMaxDynamicSharedMemorySize,
                         (int)sizeof(Smem));
    cudaFuncSetAttribute(Generator_34746285425383_kernel,
                         cudaFuncAttributeNonPortableClusterSizeAllowed, 1);

    cudaLaunchConfig_t cfg = {};
    cfg.gridDim  = dim3(CLSZ, 1, 1);
    cfg.blockDim = dim3(TPB, 1, 1);
    cfg.dynamicSmemBytes = sizeof(Smem);
    cfg.stream = 0;
    cudaLaunchAttribute attrs[1];
    attrs[0].id = cudaLaunchAttributeClusterDimension;
    attrs[0].val.clusterDim.x = CLSZ;
    attrs[0].val.clusterDim.y = 1;
    attrs[0].val.clusterDim.z = 1;
    cfg.attrs = attrs;
    cfg.numAttrs = 1;
    cudaLaunchKernelEx(&cfg, Generator_34746285425383_kernel, p);
}

// round 5
// speedup vs baseline: 1.6441x; 1.3962x over previous
#include <cuda_runtime.h>
#include <cstdint>
#include <math.h>

#define H     256
#define TPB   384
#define CLSZ  16
#define EPB   16            // h elements per CTA
#define NR    48            // gate rows per CTA (3*EPB)
#define KS    49            // padded float4 stride (bank-conflict-free)
#define MAXN  64
#define ENDN  11

// flattened f32 output layout (concat of reference tuple, row-major)
#define NPOFF 0
#define NIOFF 192
#define NVOFF 384
#define EPOFF 448
#define EIOFF 8640
#define EVOFF 16832

struct Params {
    const float *z, *lp_w, *lp_b;
    const float *nWih, *nWhh, *nbih, *nbhh;
    const float *eWih, *eWhh, *ebih, *ebhh;
    const float *nc0w, *nc0b, *nc1w, *nc1b, *nc2w, *nc2b;
    const float *ec0w, *ec0b, *ec1w, *ec1b;
    float *out;
};

struct __align__(16) Smem {
    float4 eWp[64 * KS];     // eWhh slice  packed [k4][row], padded
    float4 nWp[64 * KS];     // nWhh slice
    float4 eIp[64 * KS];     // eWih slice
    float4 nIp[64 * KS];     // nWih slice
    float  P[MAXN * NR];     // cached edge input projections (init = ebih rows)
    float  hbuf[3][H];       // triple-buffered broadcast hidden vector
    float  h1v[H];           // this step's node embedding h1
    float  hcarry[H];        // node GRU carry h
    float  xnode[H];         // buf[i-1] (input to node GRU)
    float  part[TPB];        // GEMV partials
    float  parti[TPB];       // second partials (node gi)
    float  ebhh_s[NR], nbhh_s[NR], nbih_s[NR], ebih_s[NR];
    float  logits[28];
    float  ecb[9], ncb[21];
    float  ep_ts[MAXN][2];
    int    ei_ts[MAXN][2];
    float  nprob[3];
    int    nidx[3];
    int    all_zero, done, node_ok, activ, xzero;
    unsigned long long mbar[3];
};

__device__ __forceinline__ uint32_t s2u(const void* p) {
    uint32_t r;
    asm("{ .reg .u64 t; cvta.to.shared.u64 t, %1; cvt.u32.u64 %0, t; }" : "=r"(r) : "l"(p));
    return r;
}
__device__ __forceinline__ void cluster_sync_() {
    asm volatile("barrier.cluster.arrive.aligned;" ::: "memory");
    asm volatile("barrier.cluster.wait.aligned;" ::: "memory");
}
__device__ __forceinline__ float wred(float v) {
    v += __shfl_xor_sync(0xffffffffu, v, 16);
    v += __shfl_xor_sync(0xffffffffu, v, 8);
    v += __shfl_xor_sync(0xffffffffu, v, 4);
    v += __shfl_xor_sync(0xffffffffu, v, 2);
    v += __shfl_xor_sync(0xffffffffu, v, 1);
    return v;
}
__device__ __forceinline__ float sigf(float x)  { return 1.f / (1.f + __expf(-x)); }
__device__ __forceinline__ float tanhf_(float x){ return 2.f / (1.f + __expf(-2.f * x)) - 1.f; }

__global__ void __launch_bounds__(TPB, 1)
Generator_34746285425383_kernel(Params p) {
    extern __shared__ __align__(16) unsigned char smem_raw[];
    Smem* s = reinterpret_cast<Smem*>(smem_raw);

    const int tid  = threadIdx.x;
    const int lane = tid & 31;
    const int w    = tid >> 5;
    const int q    = tid / NR;      // column-chunk (0..7), 8 float4 each
    const int r    = tid % NR;      // local gate row
    uint32_t rank;
    asm("mov.u32 %0, %%cluster_ctarank;" : "=r"(rank));
    const int gbase = (int)rank * EPB;

    const uint32_t mbase = s2u(&s->mbar[0]);
    const uint32_t hb0   = s2u(&s->hbuf[0][0]);

    auto grow = [&](int l) { return ((l >> 4) << 8) + gbase + (l & 15); };

    // ================= init =================
    {
        const float* srcs[4] = { p.eWhh, p.nWhh, p.eWih, p.nWih };
        float4* dsts[4] = { s->eWp, s->nWp, s->eIp, s->nIp };
        #pragma unroll
        for (int m = 0; m < 4; m++) {
            for (int l = w; l < NR; l += 12) {
                const float4* src = reinterpret_cast<const float4*>(srcs[m] + grow(l) * H);
                #pragma unroll
                for (int j = 0; j < 2; j++) {
                    int k4 = lane + 32 * j;
                    dsts[m][k4 * KS + l] = src[k4];
                }
            }
        }
    }
    for (int idx = tid; idx < MAXN * NR; idx += TPB)
        s->P[idx] = p.ebih[grow(idx % NR)];       // proj of zero embedding = bias
    if (tid < NR) {
        int row = grow(tid);
        s->ebhh_s[tid] = p.ebhh[row];
        s->nbhh_s[tid] = p.nbhh[row];
        s->nbih_s[tid] = p.nbih[row];
        s->ebih_s[tid] = p.ebih[row];
    }
    if (tid < 9)  s->ecb[tid] = (tid < 5) ? p.ec0b[tid] : p.ec1b[tid - 5];
    if (tid < 21) s->ncb[tid] = (tid < 12) ? p.nc0b[tid]
                               : (tid < 17) ? p.nc1b[tid - 12] : p.nc2b[tid - 17];
    if (tid < H) {
        float acc = p.lp_b[tid];
        const float* wr = p.lp_w + tid * 128;
        #pragma unroll 8
        for (int k = 0; k < 128; k++) acc = fmaf(wr[k], p.z[k], acc);
        s->hcarry[tid] = acc;
        s->xnode[tid]  = 0.f;
    }
    if (tid == 0) {
        s->done = 0; s->xzero = 1;
        #pragma unroll
        for (int b = 0; b < 3; b++)
            asm volatile("mbarrier.init.shared.b64 [%0], %1;"
                         :: "r"(mbase + b * 8u), "r"(1) : "memory");
    }

    // classifier weight rows in registers (warps 1..9)
    float ew[8], nw0[8], nw1[8], nw2[8];
    #pragma unroll
    for (int k = 0; k < 8; k++) { ew[k] = 0.f; nw0[k] = 0.f; nw1[k] = 0.f; nw2[k] = 0.f; }
    if (w >= 1 && w <= 9) {
        int wc = w - 1;
        const float* eb = (wc < 5) ? p.ec0w + wc * H : p.ec1w + (wc - 5) * H;
        auto nbase = [&](int n) {
            return (n < 12) ? p.nc0w + n * H : (n < 17) ? p.nc1w + (n - 12) * H : p.nc2w + (n - 17) * H;
        };
        const float* n0 = nbase(wc);
        const float* n1 = nbase(wc + 9);
        const float* n2 = (wc < 3) ? nbase(wc + 18) : n0;
        #pragma unroll
        for (int k = 0; k < 8; k++) {
            ew[k]  = eb[lane + 32 * k];
            nw0[k] = n0[lane + 32 * k];
            nw1[k] = n1[lane + 32 * k];
            nw2[k] = (wc < 3) ? n2[lane + 32 * k] : 0.f;
        }
    }
    __syncthreads();
    cluster_sync_();
    if (tid == 0) {
        #pragma unroll
        for (int b = 0; b < 3; b++)
            asm volatile("mbarrier.arrive.expect_tx.shared::cta.b64 _, [%0], %1;"
                         :: "r"(mbase + b * 8u), "r"(1024) : "memory");
    }

    uint32_t pmask = 0;
    auto wait_tick = [&](int b) {
        uint32_t mb = mbase + (uint32_t)b * 8u;
        uint32_t ph = (pmask >> b) & 1u;
        uint32_t done_;
        asm volatile("{\n\t.reg .pred p;\n\t"
            "mbarrier.try_wait.parity.acquire.cluster.shared::cta.b64 p, [%1], %2;\n\t"
            "selp.b32 %0, 1, 0, p;\n\t}"
            : "=r"(done_) : "r"(mb), "r"(ph) : "memory");
        while (!done_) {
            asm volatile("{\n\t.reg .pred p;\n\t"
                "mbarrier.try_wait.parity.acquire.cluster.shared::cta.b64 p, [%1], %2, 0x989680;\n\t"
                "selp.b32 %0, 1, 0, p;\n\t}"
                : "=r"(done_) : "r"(mb), "r"(ph) : "memory");
        }
        pmask ^= (1u << b);
        if (tid == 0)
            asm volatile("mbarrier.arrive.expect_tx.shared::cta.b64 _, [%0], %1;"
                         :: "r"(mb), "r"(1024) : "memory");
    };

    // warp-0: broadcast 16 h-values to all CTAs via st.async (8B packed pairs)
    auto send_h = [&](float hv, int ob) {
        int pr = lane & 7;
        float lo = __shfl_sync(0xffffffffu, hv, pr * 2);
        float hi = __shfl_sync(0xffffffffu, hv, pr * 2 + 1);
        unsigned long long val;
        asm("mov.b64 %0, {%1, %2};" : "=l"(val) : "f"(lo), "f"(hi));
        uint32_t dl = hb0 + (uint32_t)ob * (H * 4) + (uint32_t)(gbase + pr * 2) * 4;
        uint32_t ml = mbase + (uint32_t)ob * 8u;
        int rk = lane >> 3;
        #pragma unroll
        for (int kk = 0; kk < 4; kk++) {
            uint32_t da, ma;
            asm("mapa.shared::cluster.u32 %0, %1, %2;" : "=r"(da) : "r"(dl), "r"(rk));
            asm("mapa.shared::cluster.u32 %0, %1, %2;" : "=r"(ma) : "r"(ml), "r"(rk));
            asm volatile("st.async.shared::cluster.mbarrier::complete_tx::bytes.b64 [%0], %1, [%2];"
                         :: "r"(da), "l"(val), "r"(ma) : "memory");
            rk += 4;
        }
    };

    auto cls_edge = [&](const float* v) {
        if (w >= 1 && w <= 9) {
            float sum = 0.f;
            #pragma unroll
            for (int k = 0; k < 8; k++) sum = fmaf(ew[k], v[lane + 32 * k], sum);
            sum = wred(sum);
            if (lane == 0) s->logits[w - 1] = sum + s->ecb[w - 1];
        }
    };
    auto cls_node = [&](const float* v) {
        if (w >= 1 && w <= 9) {
            int wc = w - 1;
            float s0 = 0.f, s1 = 0.f, s2 = 0.f;
            #pragma unroll
            for (int k = 0; k < 8; k++) {
                float x = v[lane + 32 * k];
                s0 = fmaf(nw0[k], x, s0);
                s1 = fmaf(nw1[k], x, s1);
                s2 = fmaf(nw2[k], x, s2);
            }
            s0 = wred(s0); s1 = wred(s1); s2 = wred(s2);
            if (lane == 0) {
                s->logits[wc]     = s0 + s->ncb[wc];
                s->logits[wc + 9] = s1 + s->ncb[wc + 9];
                if (wc < 3) s->logits[wc + 18] = s2 + s->ncb[wc + 18];
            }
        }
    };
    auto soft_edge = [&](int idx, int count_az) {
        int base = lane ? 5 : 0;
        int n    = lane ? 4 : 5;
        float m = -1e30f; int b = 0;
        for (int j = 0; j < n; j++) {
            float L = s->logits[base + j];
            if (L > m) { m = L; b = j; }
        }
        float se = 0.f;
        for (int j = 0; j < n; j++) se += __expf(s->logits[base + j] - m);
        s->ei_ts[idx][lane] = b;
        s->ep_ts[idx][lane] = 1.f / se;
        if (count_az && lane == 0 && b != 0) s->all_zero = 0;
    };
    auto soft_node = [&]() {
        const int starts[3] = {0, 12, 17};
        const int cnts[3]   = {12, 5, 4};
        int base = starts[lane], n = cnts[lane];
        float m = -1e30f; int b = 0;
        for (int j = 0; j < n; j++) {
            float L = s->logits[base + j];
            if (L > m) { m = L; b = j; }
        }
        float se = 0.f;
        for (int j = 0; j < n; j++) se += __expf(s->logits[base + j] - m);
        s->nprob[lane] = 1.f / se;
        s->nidx[lane]  = b;
    };

    int sb = 1;      // buffer/mbar the next produced tick targets
    int lastb = 0;   // buffer of the most recently produced tick

    for (int i = 0; i < MAXN; i++) {
        const int xz = s->xzero;

        // ---------- node tick: produce h1 into hbuf[sb] ----------
        {
            float acc = 0.f, acci = 0.f;
            const float4* hv4 = reinterpret_cast<const float4*>(s->hcarry);
            const float4* xv4 = reinterpret_cast<const float4*>(s->xnode);
            #pragma unroll
            for (int j = 0; j < 8; j++) {
                int k4 = q * 8 + j;
                float4 wv = s->nWp[k4 * KS + r];
                float4 xx = hv4[k4];
                acc = fmaf(wv.x, xx.x, fmaf(wv.y, xx.y, fmaf(wv.z, xx.z, fmaf(wv.w, xx.w, acc))));
                if (!xz) {
                    float4 wi = s->nIp[k4 * KS + r];
                    float4 xi = xv4[k4];
                    acci = fmaf(wi.x, xi.x, fmaf(wi.y, xi.y, fmaf(wi.z, xi.z, fmaf(wi.w, xi.w, acci))));
                }
            }
            s->part[tid]  = acc;
            s->parti[tid] = acci;
            if (tid == TPB - 1) s->all_zero = 1;
        }
        __syncthreads();
        if (w == 0) {
            int e = lane & 15;
            float a0 = s->nbhh_s[e], a1 = s->nbhh_s[16 + e], a2 = s->nbhh_s[32 + e];
            float b0 = s->nbih_s[e], b1 = s->nbih_s[16 + e], b2 = s->nbih_s[32 + e];
            #pragma unroll
            for (int qq = 0; qq < 8; qq++) {
                const float* pp = s->part  + qq * NR;
                const float* pi = s->parti + qq * NR;
                a0 += pp[e]; a1 += pp[16 + e]; a2 += pp[32 + e];
                if (!xz) { b0 += pi[e]; b1 += pi[16 + e]; b2 += pi[32 + e]; }
            }
            float rg = sigf(b0 + a0);
            float zg = sigf(b1 + a1);
            float nn = tanhf_(b2 + rg * a2);
            float hold = s->hcarry[gbase + e];
            float hv = (1.f - zg) * nn + zg * hold;
            send_h(hv, sb);
        }
        lastb = sb; sb = (sb == 2) ? 0 : sb + 1;

        // ---------- edge ticks t = 0..i-1 ----------
        for (int t = 0; t < i; t++) {
            const int src = i - 1 - t;
            wait_tick(lastb);
            const float* hx = s->hbuf[lastb];
            if (t == 0)
                for (int k = tid; k < H; k += TPB) s->h1v[k] = hx[k];
            {
                float acc = 0.f;
                const float4* xv = reinterpret_cast<const float4*>(hx);
                #pragma unroll
                for (int j = 0; j < 8; j++) {
                    int k4 = q * 8 + j;
                    float4 wv = s->eWp[k4 * KS + r];
                    float4 xx = xv[k4];
                    acc = fmaf(wv.x, xx.x, fmaf(wv.y, xx.y, fmaf(wv.z, xx.z, fmaf(wv.w, xx.w, acc))));
                }
                s->part[tid] = acc;
            }
            __syncthreads();
            if (w == 0) {
                int e = lane & 15;
                float a0 = s->ebhh_s[e], a1 = s->ebhh_s[16 + e], a2 = s->ebhh_s[32 + e];
                #pragma unroll
                for (int qq = 0; qq < 8; qq++) {
                    const float* pp = s->part + qq * NR;
                    a0 += pp[e]; a1 += pp[16 + e]; a2 += pp[32 + e];
                }
                const float* Pr = s->P + src * NR;
                float rg = sigf(Pr[e] + a0);
                float zg = sigf(Pr[16 + e] + a1);
                float nn = tanhf_(Pr[32 + e] + rg * a2);
                float hold = hx[gbase + e];
                float hv = (1.f - zg) * nn + zg * hold;
                send_h(hv, sb);
            } else if (w <= 9) {
                if (t == 0) cls_node(hx); else cls_edge(hx);
                asm volatile("bar.sync 1, 288;" ::: "memory");
                if (w == 1) {
                    if (t == 0) { if (lane < 3) soft_node(); }
                    else        { if (lane < 2) soft_edge(t - 1, 1); }
                }
            }
            lastb = sb; sb = (sb == 2) ? 0 : sb + 1;
        }

        // ---------- drain ----------
        wait_tick(lastb);
        const float* hf = s->hbuf[lastb];
        if (i == 0) {
            for (int k = tid; k < H; k += TPB) s->h1v[k] = hf[k];
            cls_node(hf);
            __syncthreads();
            if (w == 1 && lane < 3) soft_node();
            __syncthreads();
        }
        cls_edge(hf);
        __syncthreads();
        if (w == 1 && lane < 2) soft_edge((i > 0) ? (i - 1) : 0, (i > 0) ? 1 : 0);
        __syncthreads();

        // ---------- decisions ----------
        if (tid == 0) {
            int is_end   = (s->nidx[0] == ENDN);
            int no_edges = (i > 0) && s->all_zero;
            int active   = !s->done;
            int nok      = active && !is_end && !no_edges;
            s->node_ok = nok;
            s->activ   = active;
            s->done    = s->done | is_end | no_edges;
            s->xzero   = !nok;
        }
        __syncthreads();
        const int nok    = s->node_ok;
        const int active = s->activ;

        if (active) {
            const float* sv = (nok && i > 0) ? hf : s->h1v;
            for (int k = tid; k < H; k += TPB) s->hcarry[k] = sv[k];
        }
        for (int k = tid; k < H; k += TPB) s->xnode[k] = nok ? s->h1v[k] : 0.f;
        __syncthreads();

        // freeze: P[i] = h1 @ eWih_rows + ebih
        if (nok) {
            float acc = 0.f;
            const float4* xv = reinterpret_cast<const float4*>(s->h1v);
            #pragma unroll
            for (int j = 0; j < 8; j++) {
                int k4 = q * 8 + j;
                float4 wv = s->eIp[k4 * KS + r];
                float4 xx = xv[k4];
                acc = fmaf(wv.x, xx.x, fmaf(wv.y, xx.y, fmaf(wv.z, xx.z, fmaf(wv.w, xx.w, acc))));
            }
            s->part[tid] = acc;
            __syncthreads();
            if (tid < NR) {
                float sg = 0.f;
                #pragma unroll
                for (int qq = 0; qq < 8; qq++) sg += s->part[qq * NR + tid];
                s->P[i * NR + tid] = sg + s->ebih_s[tid];
            }
        }
        __syncthreads();

        // ---------- outputs (rank 0) ----------
        if (rank == 0) {
            if (tid == 0) {
                #pragma unroll
                for (int c = 0; c < 3; c++) {
                    p.out[NPOFF + i * 3 + c] = nok ? s->nprob[c] : 0.f;
                    p.out[NIOFF + i * 3 + c] = (float)s->nidx[c];
                }
                p.out[NVOFF + i] = nok ? 1.f : 0.f;
            }
            if (tid < 64) {
                int j  = tid;
                int t2 = (j < i) ? (i - 1 - j) : 0;
                int ev = (j < i) && nok && (i > 0);
                p.out[EPOFF + (i * 64 + j) * 2 + 0] = ev ? s->ep_ts[t2][0] : 0.f;
                p.out[EPOFF + (i * 64 + j) * 2 + 1] = ev ? s->ep_ts[t2][1] : 0.f;
                p.out[EIOFF + (i * 64 + j) * 2 + 0] = (float)s->ei_ts[t2][0];
                p.out[EIOFF + (i * 64 + j) * 2 + 1] = (float)s->ei_ts[t2][1];
                p.out[EVOFF + i * 64 + j] = ev ? 1.f : 0.f;
            }
        }
        __syncthreads();
    }
    cluster_sync_();
}

extern "C" void kernel_launch(void* const* d_in, const int* in_sizes, int n_in,
                              void* d_out, int out_size) {
    Params p;
    p.z    = (const float*)d_in[0];
    p.lp_w = (const float*)d_in[1];
    p.lp_b = (const float*)d_in[2];
    p.nWih = (const float*)d_in[3];
    p.nWhh = (const float*)d_in[4];
    p.nbih = (const float*)d_in[5];
    p.nbhh = (const float*)d_in[6];
    p.eWih = (const float*)d_in[7];
    p.eWhh = (const float*)d_in[8];
    p.ebih = (const float*)d_in[9];
    p.ebhh = (const float*)d_in[10];
    p.nc0w = (const float*)d_in[11];
    p.nc0b = (const float*)d_in[12];
    p.nc1w = (const float*)d_in[13];
    p.nc1b = (const float*)d_in[14];
    p.nc2w = (const float*)d_in[15];
    p.nc2b = (const float*)d_in[16];
    p.ec0w = (const float*)d_in[17];
    p.ec0b = (const float*)d_in[18];
    p.ec1w = (const float*)d_in[19];
    p.ec1b = (const float*)d_in[20];
    p.out  = (float*)d_out;

    cudaFuncSetAttribute(Generator_34746285425383_kernel,
                         cudaFuncAttributeMaxDynamicSharedMemorySize,
                         (int)sizeof(Smem));
    cudaFuncSetAttribute(Generator_34746285425383_kernel,
                         cudaFuncAttributeNonPortableClusterSizeAllowed, 1);

    cudaLaunchConfig_t cfg = {};
    cfg.gridDim  = dim3(CLSZ, 1, 1);
    cfg.blockDim = dim3(TPB, 1, 1);
    cfg.dynamicSmemBytes = sizeof(Smem);
    cfg.stream = 0;
    cudaLaunchAttribute attrs[1];
    attrs[0].id = cudaLaunchAttributeClusterDimension;
    attrs[0].val.clusterDim.x = CLSZ;
    attrs[0].val.clusterDim.y = 1;
    attrs[0].val.clusterDim.z = 1;
    cfg.attrs = attrs;
    cfg.numAttrs = 1;
    cudaLaunchKernelEx(&cfg, Generator_34746285425383_kernel, p);
}